// round 9
// baseline (speedup 1.0000x reference)
#include <cuda_runtime.h>

// Quanvolution quantum filter — closed-form Heisenberg-picture evaluation.
// K coefficients computed by a 1-thread prep kernel, copied into __constant__
// memory via a graph-capturable D2D memcpy, and read through the constant
// port (LDC/LDCU) — zero shared-memory / L1 traffic for coefficients.
// Main kernel: 2 patches per thread, packed f32x2, no smem, no barriers.

#define BATCH   8192
#define NPATCH  196
#define NTOT    (BATCH * NPATCH)
#define NPAIR   (NTOT / 2)          // 802816 = 6272 * 128

typedef unsigned long long u64;

struct KBlock {
    u64   K[18];    // coefficient broadcast into both f32 lanes
    float P[4];     // params[0][v] angle shifts
};

__constant__ KBlock cKB;
__device__   KBlock gKB;

__device__ __forceinline__ u64 pk2(float lo, float hi) {
    u64 r; asm("mov.b64 %0, {%1, %2};" : "=l"(r) : "f"(lo), "f"(hi)); return r;
}
__device__ __forceinline__ u64 mul2(u64 a, u64 b) {
    u64 r; asm("mul.rn.f32x2 %0, %1, %2;" : "=l"(r) : "l"(a), "l"(b)); return r;
}
__device__ __forceinline__ u64 fma2(u64 a, u64 b, u64 c) {
    u64 r; asm("fma.rn.f32x2 %0, %1, %2, %3;" : "=l"(r) : "l"(a), "l"(b), "l"(c)); return r;
}
__device__ __forceinline__ void upk2(u64 v, float& lo, float& hi) {
    asm("mov.b64 {%0, %1}, %2;" : "=f"(lo), "=f"(hi) : "l"(v));
}

__global__ void quanv_prep(const float* __restrict__ params)
{
    float c[4], s[4];
    #pragma unroll
    for (int v = 0; v < 4; ++v) {
        gKB.P[v] = params[v];
        __sincosf(params[4 + v], &s[v], &c[v]);
    }
    float k[18];
    k[0]  =  c[1] * c[2] * c[3];          // E0: z0z1z3
    k[1]  = -c[1] * c[2] * s[3];          // E0: x0x1z2x3
    k[2]  = -s[1] * c[2] * c[3];          // E0: x1x2z3
    k[3]  = -s[1] * s[2] * s[3];          // E0: x0
    k[4]  =  c[0] * c[1];                 // E1: z0z2z3
    k[5]  =  s[0] * s[1];                 // E1: x0x2
    k[6]  =  c[0] * c[1] * c[2];          // E2: z1z3
    k[7]  = -c[0] * s[1] * c[2];          // E2: z0x1x2z3
    k[8]  = -s[0] * c[1] * c[2];          // E2: x0x1z2
    k[9]  = -s[0] * s[1] * s[2];          // E2: x0x3
    k[10] =  c[0] * c[1] * c[2] * c[3];   // E3: z0z2
    k[11] = -c[0] * c[1] * s[2] * c[3];   // E3: z1x2x3
    k[12] =  s[0] * s[1] * c[2] * c[3];   // E3: x0x2z3
    k[13] =  s[0] * c[1] * c[2] * s[3];   // E3: z2x3
    k[14] =  c[0] * s[1] * s[2] * c[3];   // E3: z0x1x3
    k[15] = -s[0] * c[1] * s[2] * s[3];   // E3: z0z1x2
    k[16] = -c[0] * s[1] * s[2] * s[3];   // E3: x0z1z2z3
    k[17] =  s[0] * s[1] * s[2] * s[3];   // E3: x1
    #pragma unroll
    for (int i = 0; i < 18; ++i) gKB.K[i] = pk2(k[i], k[i]);
}

__global__ __launch_bounds__(128, 12)
void quanv9_kernel(const float* __restrict__ x,
                   float* __restrict__ out)
{
    int q = blockIdx.x * blockDim.x + threadIdx.x;   // pair index (exact grid)
    int b  = q / 98;
    int pp = q - b * 98;
    int r  = pp / 7;
    int j  = pp - r * 7;

    const float* img = x + b * 784;
    float4 top = *reinterpret_cast<const float4*>(img + (2 * r) * 28 + 4 * j);
    float4 bot = *reinterpret_cast<const float4*>(img + (2 * r + 1) * 28 + 4 * j);

    float P0 = cKB.P[0], P1 = cKB.P[1], P2 = cKB.P[2], P3 = cKB.P[3];

    // Full angles a_v = x_v + params[0][v]; Z = cos a, X = sin a.
    float zA0, xA0, zA1, xA1, zA2, xA2, zA3, xA3;   // patch A (lo lane)
    float zB0, xB0, zB1, xB1, zB2, xB2, zB3, xB3;   // patch B (hi lane)
    __sincosf(top.x + P0, &xA0, &zA0);
    __sincosf(top.y + P1, &xA1, &zA1);
    __sincosf(bot.x + P2, &xA2, &zA2);
    __sincosf(bot.y + P3, &xA3, &zA3);
    __sincosf(top.z + P0, &xB0, &zB0);
    __sincosf(top.w + P1, &xB1, &zB1);
    __sincosf(bot.z + P2, &xB2, &zB2);
    __sincosf(bot.w + P3, &xB3, &zB3);

    u64 Z0 = pk2(zA0, zB0), X0 = pk2(xA0, xB0);
    u64 Z1 = pk2(zA1, zB1), X1 = pk2(xA1, xB1);
    u64 Z2 = pk2(zA2, zB2), X2 = pk2(xA2, xB2);
    u64 Z3 = pk2(zA3, zB3), X3 = pk2(xA3, xB3);

    // Shared pair products.
    u64 zz01 = mul2(Z0, Z1), zz02 = mul2(Z0, Z2), zz03 = mul2(Z0, Z3);
    u64 zz13 = mul2(Z1, Z3), zz23 = mul2(Z2, Z3);
    u64 xx01 = mul2(X0, X1), xx02 = mul2(X0, X2), xx03 = mul2(X0, X3);
    u64 xx12 = mul2(X1, X2), xx13 = mul2(X1, X3), xx23 = mul2(X2, X3);
    u64 zx23 = mul2(Z2, X3);

    // E[Z_0] = k0*z0z1z3 + k1*x0x1z2x3 + k2*x1x2z3 + k3*x0
    u64 e0 = mul2(cKB.K[0], mul2(zz01, Z3));
    e0 = fma2(cKB.K[1], mul2(xx01, zx23), e0);
    e0 = fma2(cKB.K[2], mul2(xx12, Z3), e0);
    e0 = fma2(cKB.K[3], X0, e0);

    // E[Z_1] = k4*z0z2z3 + k5*x0x2
    u64 e1 = mul2(cKB.K[4], mul2(Z0, zz23));
    e1 = fma2(cKB.K[5], xx02, e1);

    // E[Z_2] = k6*z1z3 + k7*z0x1x2z3 + k8*x0x1z2 + k9*x0x3
    u64 e2 = mul2(cKB.K[6], zz13);
    e2 = fma2(cKB.K[7], mul2(xx12, zz03), e2);
    e2 = fma2(cKB.K[8], mul2(xx01, Z2), e2);
    e2 = fma2(cKB.K[9], xx03, e2);

    // E[Z_3] = k10*z0z2 + k11*z1x2x3 + k12*x0x2z3 + k13*z2x3
    //        + k14*z0x1x3 + k15*z0z1x2 + k16*x0z1z2z3 + k17*x1
    u64 e3 = mul2(cKB.K[10], zz02);
    e3 = fma2(cKB.K[11], mul2(Z1, xx23), e3);
    e3 = fma2(cKB.K[12], mul2(xx02, Z3), e3);
    e3 = fma2(cKB.K[13], zx23, e3);
    e3 = fma2(cKB.K[14], mul2(Z0, xx13), e3);
    e3 = fma2(cKB.K[15], mul2(zz01, X2), e3);
    e3 = fma2(cKB.K[16], mul2(mul2(zz13, Z2), X0), e3);
    e3 = fma2(cKB.K[17], X1, e3);

    float4 o0, o1;
    upk2(e0, o0.x, o1.x);
    upk2(e1, o0.y, o1.y);
    upk2(e2, o0.z, o1.z);
    upk2(e3, o0.w, o1.w);

    int n0 = 2 * q;
    reinterpret_cast<float4*>(out)[n0]     = o0;
    reinterpret_cast<float4*>(out)[n0 + 1] = o1;
}

extern "C" void kernel_launch(void* const* d_in, const int* in_sizes, int n_in,
                              void* d_out, int out_size)
{
    const float* x      = (const float*)d_in[0];   // (8192,1,28,28) float32
    const float* params = (const float*)d_in[1];   // (2,4) float32
    float* out          = (float*)d_out;           // (8192, 784) float32

    (void)in_sizes; (void)n_in; (void)out_size;

    // 1) compute coefficients on device
    quanv_prep<<<1, 1>>>(params);

    // 2) D2D copy into constant bank (graph-capturable memcpy node)
    void* gp = nullptr;
    cudaGetSymbolAddress(&gp, gKB);
    cudaMemcpyToSymbolAsync(cKB, gp, sizeof(KBlock), 0,
                            cudaMemcpyDeviceToDevice, 0);

    // 3) main kernel
    const int threads = 128;
    const int blocks  = NPAIR / threads;           // 6272, exact
    quanv9_kernel<<<blocks, threads>>>(x, out);
}

// round 10
// speedup vs baseline: 1.1805x; 1.1805x over previous
#include <cuda_runtime.h>

// Quanvolution quantum filter — closed-form Heisenberg-picture evaluation.
// Single kernel: each thread computes the 18 layer-1 coefficient products
// itself (params fetched via two uniform __ldg's — one L1 line per warp),
// so there is NO smem, NO barrier, NO extra graph nodes.
// 2 patches per thread, packed f32x2 polynomial evaluation.

#define BATCH   8192
#define NPATCH  196
#define NTOT    (BATCH * NPATCH)
#define NPAIR   (NTOT / 2)          // 802816 = 6272 * 128

typedef unsigned long long u64;

__device__ __forceinline__ u64 pk2(float lo, float hi) {
    u64 r; asm("mov.b64 %0, {%1, %2};" : "=l"(r) : "f"(lo), "f"(hi)); return r;
}
__device__ __forceinline__ u64 bc2(float v) { return pk2(v, v); }
__device__ __forceinline__ u64 mul2(u64 a, u64 b) {
    u64 r; asm("mul.rn.f32x2 %0, %1, %2;" : "=l"(r) : "l"(a), "l"(b)); return r;
}
__device__ __forceinline__ u64 fma2(u64 a, u64 b, u64 c) {
    u64 r; asm("fma.rn.f32x2 %0, %1, %2, %3;" : "=l"(r) : "l"(a), "l"(b), "l"(c)); return r;
}
__device__ __forceinline__ void upk2(u64 v, float& lo, float& hi) {
    asm("mov.b64 {%0, %1}, %2;" : "=f"(lo), "=f"(hi) : "l"(v));
}

__global__ __launch_bounds__(128, 12)
void quanv10_kernel(const float* __restrict__ x,
                    const float* __restrict__ params,
                    float* __restrict__ out)
{
    int q = blockIdx.x * blockDim.x + threadIdx.x;   // pair index (exact grid)
    int b  = q / 98;
    int pp = q - b * 98;
    int r  = pp / 7;
    int j  = pp - r * 7;

    const float* img = x + b * 784;
    float4 top = *reinterpret_cast<const float4*>(img + (2 * r) * 28 + 4 * j);
    float4 bot = *reinterpret_cast<const float4*>(img + (2 * r + 1) * 28 + 4 * j);

    // Uniform parameter fetch: one L1 line per warp, broadcast.
    float4 Pv = __ldg(reinterpret_cast<const float4*>(params));       // layer-0
    float4 Qv = __ldg(reinterpret_cast<const float4*>(params) + 1);   // layer-1

    // Layer-1 trig + coefficient products (per-thread, registers only).
    float c0, s0, c1, s1, c2, s2, c3, s3;
    __sincosf(Qv.x, &s0, &c0);
    __sincosf(Qv.y, &s1, &c1);
    __sincosf(Qv.z, &s2, &c2);
    __sincosf(Qv.w, &s3, &c3);

    float c01 = c0 * c1, s01 = s0 * s1, c0s1 = c0 * s1, s0c1 = s0 * c1;
    float c23 = c2 * c3, s23 = s2 * s3, c2s3 = c2 * s3, s2c3 = s2 * c3;

    u64 k0  = bc2( c1 * c23);      // E0: z0z1z3
    u64 k1  = bc2(-c1 * c2s3);     // E0: x0x1z2x3
    u64 k2  = bc2(-s1 * c23);      // E0: x1x2z3
    u64 k3  = bc2(-s1 * s23);      // E0: x0
    u64 k4  = bc2( c01);           // E1: z0z2z3
    u64 k5  = bc2( s01);           // E1: x0x2
    u64 k6  = bc2( c01 * c2);      // E2: z1z3
    u64 k7  = bc2(-c0s1 * c2);     // E2: z0x1x2z3
    u64 k8  = bc2(-s0c1 * c2);     // E2: x0x1z2
    u64 k9  = bc2(-s01 * s2);      // E2: x0x3
    u64 k10 = bc2( c01 * c23);     // E3: z0z2
    u64 k11 = bc2(-c01 * s2c3);    // E3: z1x2x3
    u64 k12 = bc2( s01 * c23);     // E3: x0x2z3
    u64 k13 = bc2( s0c1 * c2s3);   // E3: z2x3
    u64 k14 = bc2( c0s1 * s2c3);   // E3: z0x1x3
    u64 k15 = bc2(-s0c1 * s23);    // E3: z0z1x2
    u64 k16 = bc2(-c0s1 * s23);    // E3: x0z1z2z3
    u64 k17 = bc2( s01 * s23);     // E3: x1

    // Full angles a_v = x_v + params[0][v]; Z = cos a, X = sin a.
    float zA0, xA0, zA1, xA1, zA2, xA2, zA3, xA3;   // patch A (lo lane)
    float zB0, xB0, zB1, xB1, zB2, xB2, zB3, xB3;   // patch B (hi lane)
    __sincosf(top.x + Pv.x, &xA0, &zA0);
    __sincosf(top.y + Pv.y, &xA1, &zA1);
    __sincosf(bot.x + Pv.z, &xA2, &zA2);
    __sincosf(bot.y + Pv.w, &xA3, &zA3);
    __sincosf(top.z + Pv.x, &xB0, &zB0);
    __sincosf(top.w + Pv.y, &xB1, &zB1);
    __sincosf(bot.z + Pv.z, &xB2, &zB2);
    __sincosf(bot.w + Pv.w, &xB3, &zB3);

    u64 Z0 = pk2(zA0, zB0), X0 = pk2(xA0, xB0);
    u64 Z1 = pk2(zA1, zB1), X1 = pk2(xA1, xB1);
    u64 Z2 = pk2(zA2, zB2), X2 = pk2(xA2, xB2);
    u64 Z3 = pk2(zA3, zB3), X3 = pk2(xA3, xB3);

    // Shared pair products.
    u64 zz01 = mul2(Z0, Z1), zz02 = mul2(Z0, Z2), zz03 = mul2(Z0, Z3);
    u64 zz13 = mul2(Z1, Z3), zz23 = mul2(Z2, Z3);
    u64 xx01 = mul2(X0, X1), xx02 = mul2(X0, X2), xx03 = mul2(X0, X3);
    u64 xx12 = mul2(X1, X2), xx13 = mul2(X1, X3), xx23 = mul2(X2, X3);
    u64 zx23 = mul2(Z2, X3);

    // E[Z_0] = k0*z0z1z3 + k1*x0x1z2x3 + k2*x1x2z3 + k3*x0
    u64 e0 = mul2(k0, mul2(zz01, Z3));
    e0 = fma2(k1, mul2(xx01, zx23), e0);
    e0 = fma2(k2, mul2(xx12, Z3), e0);
    e0 = fma2(k3, X0, e0);

    // E[Z_1] = k4*z0z2z3 + k5*x0x2
    u64 e1 = mul2(k4, mul2(Z0, zz23));
    e1 = fma2(k5, xx02, e1);

    // E[Z_2] = k6*z1z3 + k7*z0x1x2z3 + k8*x0x1z2 + k9*x0x3
    u64 e2 = mul2(k6, zz13);
    e2 = fma2(k7, mul2(xx12, zz03), e2);
    e2 = fma2(k8, mul2(xx01, Z2), e2);
    e2 = fma2(k9, xx03, e2);

    // E[Z_3] = k10*z0z2 + k11*z1x2x3 + k12*x0x2z3 + k13*z2x3
    //        + k14*z0x1x3 + k15*z0z1x2 + k16*x0z1z2z3 + k17*x1
    u64 e3 = mul2(k10, zz02);
    e3 = fma2(k11, mul2(Z1, xx23), e3);
    e3 = fma2(k12, mul2(xx02, Z3), e3);
    e3 = fma2(k13, zx23, e3);
    e3 = fma2(k14, mul2(Z0, xx13), e3);
    e3 = fma2(k15, mul2(zz01, X2), e3);
    e3 = fma2(k16, mul2(mul2(zz13, Z2), X0), e3);
    e3 = fma2(k17, X1, e3);

    float4 o0, o1;
    upk2(e0, o0.x, o1.x);
    upk2(e1, o0.y, o1.y);
    upk2(e2, o0.z, o1.z);
    upk2(e3, o0.w, o1.w);

    int n0 = 2 * q;
    reinterpret_cast<float4*>(out)[n0]     = o0;
    reinterpret_cast<float4*>(out)[n0 + 1] = o1;
}

extern "C" void kernel_launch(void* const* d_in, const int* in_sizes, int n_in,
                              void* d_out, int out_size)
{
    const float* x      = (const float*)d_in[0];   // (8192,1,28,28) float32
    const float* params = (const float*)d_in[1];   // (2,4) float32
    float* out          = (float*)d_out;           // (8192, 784) float32

    (void)in_sizes; (void)n_in; (void)out_size;

    const int threads = 128;
    const int blocks  = NPAIR / threads;           // 6272, exact
    quanv10_kernel<<<blocks, threads>>>(x, params, out);
}